// round 13
// baseline (speedup 1.0000x reference)
#include <cuda_runtime.h>
#include <cuda_bf16.h>
#include <cuda_fp16.h>
#include <cstdint>

// ---------------- problem dims ----------------
#define BB 8
#define SS 2048
#define HH 1024
#define LL 4
#define MM (BB * SS)       // 16384
#define N2H (2 * HH)       // 2048
#define KK 1024

// scan chunking
#define NC 32
#define CS (SS / NC)       // 64
#define NCH (BB * HH)      // 8192

// GEMM tiling: CTA 128x128, 4 warps, warp tile 64x64, BK=64
#define BM 128
#define BN 128
#define BK 64
#define NKIT (KK / BK)     // 16

#define MAT_B (BM * 128)                // 16384 bytes per tile (128B rows)
#define STAGE_B (2 * MAT_B)             // A, W = 32768
#define NSTAGE 3
#define SMEM_TOTAL (NSTAGE * STAGE_B)   // 98304 -> 2 CTAs/SM

// SW128 swizzle for 128B rows: XOR bits[6:4] with bits[9:7].
// Row deltas (multiples of 2048) commute; k-step deltas do NOT.
#define SWZ(off) ((off) ^ (((off) >> 3) & 0x70))

#define WSCALE 64.0f
#define WINV   0.015625f

// ---------------- scratch (device globals; allocation banned) ----------------
__device__ __half  g_gh  [(size_t)MM * N2H];    // fp16 gate|hidden
__device__ __half  g_ahi [(size_t)MM * KK];     // residual hi (GEMM operand)
__device__ __half  g_alo [(size_t)MM * KK];     // residual lo
__device__ __half  g_w16 [(size_t)LL * N2H * KK];
__device__ float   g_C   [(size_t)NC * NCH];
__device__ float   g_V   [(size_t)NC * NCH];
__device__ float   g_hin [(size_t)NC * NCH];

// ---------------- PTX helpers ----------------
__device__ __forceinline__ uint32_t smem_u32(const void* p) {
    uint32_t a;
    asm("{ .reg .u64 t; cvta.to.shared.u64 t, %1; cvt.u32.u64 %0, t; }"
        : "=r"(a) : "l"(p));
    return a;
}
__device__ __forceinline__ void cp16(uint32_t s, const void* g) {
    asm volatile("cp.async.cg.shared.global [%0], [%1], 16;" :: "r"(s), "l"(g));
}
__device__ __forceinline__ void cp_commit() {
    asm volatile("cp.async.commit_group;" ::: "memory");
}
template <int N>
__device__ __forceinline__ void cp_wait() {
    asm volatile("cp.async.wait_group %0;" :: "n"(N) : "memory");
}
__device__ __forceinline__ void ldsm4(uint32_t* r, uint32_t addr) {
    asm volatile("ldmatrix.sync.aligned.m8n8.x4.shared.b16 {%0,%1,%2,%3}, [%4];"
                 : "=r"(r[0]), "=r"(r[1]), "=r"(r[2]), "=r"(r[3]) : "r"(addr));
}
__device__ __forceinline__ void mma16816(float* c, const uint32_t* a, const uint32_t* b) {
    asm volatile(
        "mma.sync.aligned.m16n8k16.row.col.f32.f16.f16.f32 "
        "{%0,%1,%2,%3}, {%4,%5,%6,%7}, {%8,%9}, {%0,%1,%2,%3};"
        : "+f"(c[0]), "+f"(c[1]), "+f"(c[2]), "+f"(c[3])
        : "r"(a[0]), "r"(a[1]), "r"(a[2]), "r"(a[3]), "r"(b[0]), "r"(b[1]));
}

// ---------------- converts ----------------
__global__ __launch_bounds__(256) void tof16_kernel(
    const float4* __restrict__ in, uint2* __restrict__ o16, float scale, int n4)
{
    int i = blockIdx.x * blockDim.x + threadIdx.x;
    if (i >= n4) return;
    float4 v = in[i];
    uint2 H;
    H.x = (uint32_t)__half_as_ushort(__float2half(v.x * scale))
        | ((uint32_t)__half_as_ushort(__float2half(v.y * scale)) << 16);
    H.y = (uint32_t)__half_as_ushort(__float2half(v.z * scale))
        | ((uint32_t)__half_as_ushort(__float2half(v.w * scale)) << 16);
    o16[i] = H;
}

// ---------------- mma.sync GEMM: gh = fp16((A * (64W)^T)/64 + bias) ----------
// 4 warps, warp tile 64x64 (halved ldsm bytes per MMA vs 32x64).
__global__ __launch_bounds__(128, 2) void gemm_mma(
    const __half* __restrict__ Af, const __half* __restrict__ Wf,
    const float* __restrict__ bias, __half* __restrict__ C)
{
    extern __shared__ __align__(1024) char smem[];
    const uint32_t sbase = smem_u32(smem);

    const int tid = threadIdx.x;
    const int wid = tid >> 5;
    const int lane = tid & 31;
    const int wm = wid & 1;         // M half (rows wm*64)
    const int wn = wid >> 1;        // N half (cols wn*64)
    const int row0 = blockIdx.y * BM;
    const int col0 = blockIdx.x * BN;

    // loader: tile = 128 rows x 128B = 1024 x 16B chunks; 8 per thread per tile
    uint32_t so[8]; size_t go[8];
#pragma unroll
    for (int j = 0; j < 8; j++) {
        const int i = tid + 128 * j;
        const int r = i >> 3, c = i & 7;
        so[j] = SWZ((uint32_t)(r * 128 + c * 16));
        go[j] = (size_t)r * KK + c * 8;
    }

    const __half* Ap = Af + (size_t)row0 * KK;
    const __half* Wp = Wf + (size_t)col0 * KK;

    auto load_stage = [&](int kt, int s) {
        const uint32_t st = sbase + s * STAGE_B;
        const int kof = kt * BK;
#pragma unroll
        for (int j = 0; j < 8; j++) {
            cp16(st + so[j],         Ap + go[j] + kof);
            cp16(st + MAT_B + so[j], Wp + go[j] + kof);
        }
        cp_commit();
    };

    float acc[4][8][4];
#pragma unroll
    for (int t = 0; t < 4; t++)
#pragma unroll
        for (int n = 0; n < 8; n++)
#pragma unroll
            for (int q = 0; q < 4; q++) acc[t][n][q] = 0.0f;

    // per-lane swizzled fragment bases, one per k16 step (4 per kt)
    const int arow = ((lane >> 3) & 1) * 8 + (lane & 7);
    const int akof = (lane >> 4) * 16;
    const int brow = ((lane >> 4) & 1) * 8 + (lane & 7);
    const int bkof = ((lane >> 3) & 1) * 16;
    const uint32_t araw = (uint32_t)((wm * 64 + arow) * 128 + akof);
    const uint32_t braw = (uint32_t)((wn * 64 + brow) * 128 + bkof);
    uint32_t aswz[4], bswz[4];
#pragma unroll
    for (int ks = 0; ks < 4; ks++) {
        aswz[ks] = SWZ(araw + ks * 32);
        bswz[ks] = SWZ(braw + ks * 32);
    }

    load_stage(0, 0);
    load_stage(1, 1);

    int cs = 0, ls = 2;
    for (int kt = 0; kt < NKIT; kt++) {
        cp_wait<1>();
        __syncthreads();

        const uint32_t stg = sbase + cs * STAGE_B;
        const uint32_t wbs = stg + MAT_B;
        if (++cs == NSTAGE) cs = 0;

        uint32_t ah[2][4][4], bf[2][4];

        // ldsm burst first (tensor pipe restarts ASAP)...
        ldsm4(ah[0][0], stg + aswz[0]);
        ldsm4(ah[0][1], stg + aswz[0] + 2048);
        ldsm4(ah[0][2], stg + aswz[0] + 4096);
        ldsm4(ah[0][3], stg + aswz[0] + 6144);
        ldsm4(bf[0], wbs + bswz[0]);

        // ...then the global->smem prefetch for kt+2
        if (kt + 2 < NKIT) {
            load_stage(kt + 2, ls);
            if (++ls == NSTAGE) ls = 0;
        }

#pragma unroll
        for (int ks = 0; ks < 4; ks++) {
            const int kb = ks & 1, nb = kb ^ 1;
#pragma unroll
            for (int p = 0; p < 4; p++) {
                // next B fragment (rolling into next ks at the seam)
                if (p < 3)        ldsm4(bf[(p + 1) & 1], wbs + bswz[ks] + (p + 1) * 2048);
                else if (ks < 3)  ldsm4(bf[(p + 1) & 1], wbs + bswz[ks + 1]);
                // next-ks A fragments interleaved through the p loop
                if (ks < 3) ldsm4(ah[nb][p], stg + aswz[ks + 1] + p * 2048);
                const uint32_t* r4 = bf[p & 1];
#pragma unroll
                for (int t = 0; t < 4; t++) {
                    mma16816(acc[t][2 * p],     ah[kb][t], r4);
                    mma16816(acc[t][2 * p + 1], ah[kb][t], r4 + 2);
                }
            }
        }
    }

    // epilogue: scale, bias, convert to fp16, store half2 pairs
    const int erow = row0 + wm * 64 + (lane >> 2);
    const int ecol0 = col0 + wn * 64 + 2 * (lane & 3);
#pragma unroll
    for (int t = 0; t < 4; t++) {
#pragma unroll
        for (int n = 0; n < 8; n++) {
            const int col = ecol0 + n * 8;
            const float2 bv = *(const float2*)(bias + col);
            __half2 h0 = __floats2half2_rn(fmaf(acc[t][n][0], WINV, bv.x),
                                           fmaf(acc[t][n][1], WINV, bv.y));
            __half2 h1 = __floats2half2_rn(fmaf(acc[t][n][2], WINV, bv.x),
                                           fmaf(acc[t][n][3], WINV, bv.y));
            *(__half2*)(C + (size_t)(erow + t * 16) * N2H + col) = h0;
            *(__half2*)(C + (size_t)(erow + t * 16 + 8) * N2H + col) = h1;
        }
    }
}

// ---------------- scan ----------------
__device__ __forceinline__ void gate_cd(float gate, float hid, float& c, float& d) {
    const float t = __expf(-gate);
    const float inv = __fdividef(1.0f, 1.0f + t);
    c = t * inv;                  // 1 - sigmoid(gate)
    const float gx = (hid >= 0.0f) ? (hid + 0.5f)
                                   : __fdividef(1.0f, 1.0f + __expf(-hid));
    d = inv * gx;                 // sigmoid(gate) * g(hid)
}

__global__ __launch_bounds__(128) void scan1_kernel(
    const __half* __restrict__ gh, float* __restrict__ Co, float* __restrict__ Vo)
{
    const int idx = blockIdx.x * blockDim.x + threadIdx.x;
    const int hh = idx & (HH - 1);
    const int rest = idx >> 10;
    const int chunk = rest & (NC - 1);
    const int b = rest >> 5;

    const __half* g = gh + (size_t)(b * SS + chunk * CS) * N2H + hh;
    float Ca = 1.0f, Va = 0.0f;
#pragma unroll 4
    for (int s = 0; s < CS; s++) {
        float c, d;
        gate_cd(__half2float(g[(size_t)s * N2H]),
                __half2float(g[(size_t)s * N2H + HH]), c, d);
        Ca *= c;
        Va = c * Va + d;
    }
    const int ch = b * HH + hh;
    Co[chunk * NCH + ch] = Ca;
    Vo[chunk * NCH + ch] = Va;
}

__global__ __launch_bounds__(128) void scan2_kernel(
    const float* __restrict__ Co, const float* __restrict__ Vo,
    const float* __restrict__ hprev, float* __restrict__ hin,
    float* __restrict__ finals)
{
    const int ch = blockIdx.x * blockDim.x + threadIdx.x;
    const float hp = hprev[ch];
    float h = (hp >= 0.0f) ? (hp + 0.5f) : __fdividef(1.0f, 1.0f + __expf(-hp));
#pragma unroll
    for (int k = 0; k < NC; k++) {
        hin[k * NCH + ch] = h;
        h = Co[k * NCH + ch] * h + Vo[k * NCH + ch];
    }
    finals[ch] = h;
}

// pass 3: recompute with h_in; residual = fp16 hi/lo pair (x = hi+lo);
// layer0 reads fp32 x; last layer writes fp32 out; middle layers update
// the hi/lo pair in place (hi is the next GEMM's A operand).
__global__ __launch_bounds__(128) void scan3_kernel(
    const __half* __restrict__ gh, const float* __restrict__ inpF,
    __half* __restrict__ ihi, __half* __restrict__ ilo,
    const float* __restrict__ hin, float* __restrict__ outF)
{
    const int idx = blockIdx.x * blockDim.x + threadIdx.x;
    const int hh = idx & (HH - 1);
    const int rest = idx >> 10;
    const int chunk = rest & (NC - 1);
    const int b = rest >> 5;
    const int ch = b * HH + hh;

    const size_t base2h = (size_t)(b * SS + chunk * CS) * N2H + hh;
    const size_t base1h = (size_t)(b * SS + chunk * CS) * HH + hh;
    const __half* g = gh + base2h;

    float h = hin[chunk * NCH + ch];
#pragma unroll 4
    for (int s = 0; s < CS; s++) {
        float c, d;
        gate_cd(__half2float(g[(size_t)s * N2H]),
                __half2float(g[(size_t)s * N2H + HH]), c, d);
        h = c * h + d;
        const size_t p = base1h + (size_t)s * HH;
        const float xin = inpF ? inpF[p]
                               : (__half2float(ihi[p]) + __half2float(ilo[p]));
        const float o = h + xin;
        if (outF) {
            outF[p] = o;
        } else {
            const __half hb = __float2half(o);
            ihi[p] = hb;
            ilo[p] = __float2half(o - __half2float(hb));
        }
    }
}

// ---------------- launch ----------------
extern "C" void kernel_launch(void* const* d_in, const int* in_sizes, int n_in,
                              void* d_out, int out_size)
{
    const float* x  = (const float*)d_in[0];  // (B,S,D)
    const float* h0 = (const float*)d_in[1];  // (L,B,1,H)
    const float* W0 = (const float*)d_in[2];  // (2H,D)
    const float* b0 = (const float*)d_in[3];  // (2H,)
    const float* Wl = (const float*)d_in[4];  // (L-1,2H,H)
    const float* bl = (const float*)d_in[5];  // (L-1,2H)

    float* out    = (float*)d_out;
    float* finals = out + (size_t)MM * HH;

    float *Cb, *Vb, *hinb;
    __half *gh, *ahi, *alo, *w16;
    cudaGetSymbolAddress((void**)&gh,   g_gh);
    cudaGetSymbolAddress((void**)&ahi,  g_ahi);
    cudaGetSymbolAddress((void**)&alo,  g_alo);
    cudaGetSymbolAddress((void**)&w16,  g_w16);
    cudaGetSymbolAddress((void**)&Cb,   g_C);
    cudaGetSymbolAddress((void**)&Vb,   g_V);
    cudaGetSymbolAddress((void**)&hinb, g_hin);

    cudaFuncSetAttribute(gemm_mma, cudaFuncAttributeMaxDynamicSharedMemorySize, SMEM_TOTAL);

    // x -> fp16 (GEMM operand only); weights -> fp16 of 64*W
    {
        int n4 = (MM * KK) / 4;
        tof16_kernel<<<(n4 + 255) / 256, 256>>>((const float4*)x, (uint2*)ahi, 1.0f, n4);
        n4 = (N2H * KK) / 4;
        tof16_kernel<<<(n4 + 255) / 256, 256>>>((const float4*)W0, (uint2*)w16, WSCALE, n4);
        n4 = (3 * N2H * KK) / 4;
        tof16_kernel<<<(n4 + 255) / 256, 256>>>((const float4*)Wl,
                                                (uint2*)(w16 + (size_t)N2H * KK), WSCALE, n4);
    }

    const dim3 ggrid(N2H / BN, MM / BM);           // (16, 128)
    const int scan13_blocks = (NCH * NC) / 128;    // 2048
    const int scan2_blocks = NCH / 128;            // 64

    for (int l = 0; l < LL; l++) {
        const __half* Wll = w16 + (size_t)l * N2H * KK;
        const float* bb = (l == 0) ? b0 : (bl + (size_t)(l - 1) * N2H);

        gemm_mma<<<ggrid, 128, SMEM_TOTAL>>>(ahi, Wll, bb, gh);

        scan1_kernel<<<scan13_blocks, 128>>>(gh, Cb, Vb);
        scan2_kernel<<<scan2_blocks, 128>>>(Cb, Vb, h0 + (size_t)l * NCH, hinb,
                                            finals + (size_t)l * NCH);

        scan3_kernel<<<scan13_blocks, 128>>>(gh, (l == 0) ? x : nullptr,
                                             ahi, alo, hinb,
                                             (l == LL - 1) ? out : nullptr);
    }
}